// round 5
// baseline (speedup 1.0000x reference)
#include <cuda_runtime.h>
#include <cstdint>
#include <cstddef>

#define BATCH   16384
#define EXPERTS 8
#define DIM     1024

// ---------------- scratch (device globals; no allocations allowed) ----------
__device__ float g_combined[(size_t)BATCH * DIM];                 //  67 MB
__device__ float g_w1t[(size_t)EXPERTS * DIM * DIM];              //  33.5 MB (k-pair interleaved)
__device__ float g_w2t[(size_t)EXPERTS * DIM * DIM];              //  33.5 MB (k-pair interleaved)
__device__ float g_h[(size_t)EXPERTS * BATCH * DIM];              // 537 MB
__device__ float g_y[(size_t)EXPERTS * BATCH * DIM];              // 537 MB
__device__ float g_wts[(size_t)BATCH * EXPERTS];                  // 0.5 MB

// ---------------- helpers ---------------------------------------------------
__device__ __forceinline__ unsigned smem_u32(const void* p) {
    return (unsigned)__cvta_generic_to_shared(p);
}

__device__ __forceinline__ float tf32_rna(float x) {
    unsigned u;
    asm("cvt.rna.tf32.f32 %0, %1;" : "=r"(u) : "f"(x));
    return __uint_as_float(u);
}

__device__ __forceinline__ void cp_async16(unsigned dst, const void* src) {
    asm volatile("cp.async.cg.shared.global [%0], [%1], 16;\n" :: "r"(dst), "l"(src));
}
__device__ __forceinline__ void cp_commit() {
    asm volatile("cp.async.commit_group;\n");
}
template <int N>
__device__ __forceinline__ void cp_wait() {
    asm volatile("cp.async.wait_group %0;\n" :: "n"(N));
}

__device__ __forceinline__ void mma_tf32(float* d, const unsigned* a, const unsigned* b) {
    asm volatile(
        "mma.sync.aligned.m16n8k8.row.col.f32.tf32.tf32.f32 "
        "{%0,%1,%2,%3}, {%4,%5,%6,%7}, {%8,%9}, {%0,%1,%2,%3};\n"
        : "+f"(d[0]), "+f"(d[1]), "+f"(d[2]), "+f"(d[3])
        : "r"(a[0]), "r"(a[1]), "r"(a[2]), "r"(a[3]), "r"(b[0]), "r"(b[1]));
}

__device__ __forceinline__ float gelu_exact(float x) {
    return 0.5f * x * (1.0f + erff(x * 0.70710678118654752f));
}

// ---------------- prep kernels ----------------------------------------------
__global__ void concat_round_kernel(const float* __restrict__ z_s,
                                    const float* __restrict__ z_e,
                                    float* __restrict__ dst) {
    size_t f = ((size_t)blockIdx.x * 256 + threadIdx.x) * 4;   // float4 index
    size_t b = f >> 10;
    int col = (int)(f & 1023);
    float4 v;
    if (col < 512) v = *(const float4*)(z_s + b * 512 + col);
    else           v = *(const float4*)(z_e + b * 512 + (col - 512));
    v.x = tf32_rna(v.x); v.y = tf32_rna(v.y);
    v.z = tf32_rna(v.z); v.w = tf32_rna(v.w);
    *(float4*)(dst + f) = v;
}

// W [e][k][n] row-major  ->  Wt [e][p][n][h]   (p = k/2, h = k&1), tf32-rounded.
// One thread emits one 16B chunk = (p, n, h=0/1) and (p, n+1, h=0/1).
__global__ void interleave_round_kernel(const float* __restrict__ W,
                                        float* __restrict__ Wt) {
    size_t c = (size_t)blockIdx.x * 256 + threadIdx.x;  // float4 chunk index
    size_t e   = c >> 18;                               // 2^18 chunks per expert
    size_t rem = c & ((1u << 18) - 1);
    int p  = (int)(rem >> 9);                           // 512 chunks per pair-row
    int n  = (int)(rem & 511) * 2;
    const float* We = W + e * (size_t)DIM * DIM;
    float4 v;
    v.x = tf32_rna(We[(size_t)(2 * p)     * DIM + n]);
    v.y = tf32_rna(We[(size_t)(2 * p + 1) * DIM + n]);
    v.z = tf32_rna(We[(size_t)(2 * p)     * DIM + n + 1]);
    v.w = tf32_rna(We[(size_t)(2 * p + 1) * DIM + n + 1]);
    *(float4*)(Wt + c * 4) = v;
}

// ---------------- router (softmax gates) ------------------------------------
__global__ __launch_bounds__(256) void router_kernel(const float* __restrict__ z_s,
                                                     const float* __restrict__ z_e,
                                                     const float* __restrict__ rw,
                                                     const float* __restrict__ rb,
                                                     float* __restrict__ wts) {
    int warp = threadIdx.x >> 5, lane = threadIdx.x & 31;
    int b = blockIdx.x * 8 + warp;
    const float* zs = z_s + (size_t)b * 512;
    const float* ze = z_e + (size_t)b * 512;
    float acc[8];
#pragma unroll
    for (int e = 0; e < 8; ++e) acc[e] = 0.f;
    for (int c = lane; c < 1024; c += 32) {
        float x = (c < 512) ? zs[c] : ze[c - 512];
        float4 wa = *(const float4*)(rw + (size_t)c * 8);
        float4 wb = *(const float4*)(rw + (size_t)c * 8 + 4);
        acc[0] += x * wa.x; acc[1] += x * wa.y; acc[2] += x * wa.z; acc[3] += x * wa.w;
        acc[4] += x * wb.x; acc[5] += x * wb.y; acc[6] += x * wb.z; acc[7] += x * wb.w;
    }
#pragma unroll
    for (int e = 0; e < 8; ++e)
#pragma unroll
        for (int off = 16; off; off >>= 1)
            acc[e] += __shfl_xor_sync(0xffffffffu, acc[e], off);
    if (lane == 0) {
        float l[8], m = -1e30f;
#pragma unroll
        for (int e = 0; e < 8; ++e) { l[e] = acc[e] + rb[e]; m = fmaxf(m, l[e]); }
        float s = 0.f;
#pragma unroll
        for (int e = 0; e < 8; ++e) { l[e] = expf(l[e] - m); s += l[e]; }
        float inv = 1.0f / s;
#pragma unroll
        for (int e = 0; e < 8; ++e) wts[(size_t)b * 8 + e] = l[e] * inv;
    }
}

// ---------------- tf32 tensor-core GEMM -------------------------------------
// C[e] = A[e] (M x K=1024, row-major) @ W[e] (K x N=1024) + bias
// block tile 128x128, k-chunk 32, 8 warps (2x4), warp tile 64x32 of m16n8k8.
// k-slot remap: mma step s, thread cq, half h  <->  global k = 8s + 2*cq + h.
//   A: thread k-pair column-adjacent in As            -> LDS.64
//   B: weights pre-interleaved (k-pair adjacent in n) -> LDS.64
// Bank math: A stride 40 floats; B pair-row stride 264 floats (132 x 8B).
// __launch_bounds__(256,2): cap regs at 128 so 2 CTAs/SM are resident
// (2 x 74.75KB smem fits 228KB) -> 4 warps/SMSP for latency hiding.
#define A_STRIDE 40
#define B_STRIDE 264                       /* floats per pair-row (132 x 8B) */
#define A_STAGE_BYTES (128 * A_STRIDE * 4) /* 20480 */
#define B_STAGE_BYTES (16 * B_STRIDE * 4)  /* 16896 */
#define SMEM_FLOATS (2 * 128 * A_STRIDE + 2 * 16 * B_STRIDE)
#define SMEM_BYTES  (SMEM_FLOATS * 4)

__global__ __launch_bounds__(256, 2) void gemm_tf32_kernel(
    const float* __restrict__ Abase, size_t a_estride,
    const float* __restrict__ Wtbase,
    const float* __restrict__ biasBase,
    float* __restrict__ Cbase, size_t c_estride,
    int do_gelu)
{
    extern __shared__ float sm[];
    float (*As)[128][A_STRIDE] = reinterpret_cast<float (*)[128][A_STRIDE]>(sm);
    float (*Bs)[16][B_STRIDE]  = reinterpret_cast<float (*)[16][B_STRIDE]>(sm + 2 * 128 * A_STRIDE);

    const int e = blockIdx.z;
    const float* A    = Abase + (size_t)e * a_estride;
    const float* Wt   = Wtbase + (size_t)e * DIM * DIM;
    const float* bias = biasBase + (size_t)e * DIM;
    float* C          = Cbase + (size_t)e * c_estride;

    const int n0 = blockIdx.x * 128;
    const int m0 = blockIdx.y * 128;
    const int tid = threadIdx.x;
    const int warp = tid >> 5, lane = tid & 31;
    const int wm = (warp >> 2) * 64;      // 2 warps in M
    const int wn = (warp & 3) * 32;       // 4 warps in N
    const int g  = lane >> 2, cq = lane & 3;

    // per-thread copy descriptors (stage-0 smem addrs; stage 1 = +stage bytes)
    const float* gA[4]; unsigned dA0[4];
    const float* gB[4]; unsigned dB0[4];
#pragma unroll
    for (int i = 0; i < 4; ++i) {
        int f   = tid + i * 256;
        int row = f >> 3, k4 = (f & 7) * 4;
        gA[i]   = A + (size_t)(m0 + row) * DIM + k4;
        dA0[i]  = smem_u32(&As[0][row][k4]);
        // B: 16B chunk f covers pair-row p = f>>6, columns n..n+1, both halves.
        int p = f >> 6, nn = (f & 63) * 2;
        gB[i]   = Wt + ((size_t)p * DIM + n0 + nn) * 2;
        dB0[i]  = smem_u32(&Bs[0][p][nn * 2]);
    }

    float acc[4][4][4];
#pragma unroll
    for (int a = 0; a < 4; ++a)
#pragma unroll
        for (int b = 0; b < 4; ++b)
#pragma unroll
            for (int k = 0; k < 4; ++k) acc[a][b][k] = 0.f;

    auto copy_chunk = [&](int k0, int buf) {
        const unsigned ao = buf * A_STAGE_BYTES, bo = buf * B_STAGE_BYTES;
#pragma unroll
        for (int i = 0; i < 4; ++i) cp_async16(dA0[i] + ao, gA[i] + k0);
        // chunk advance in Wt: 16 pair-rows * 1024 n * 2 halves = k0 * DIM floats
#pragma unroll
        for (int i = 0; i < 4; ++i) cp_async16(dB0[i] + bo, gB[i] + (size_t)k0 * DIM);
    };

    copy_chunk(0, 0);
    cp_commit();

#pragma unroll 1
    for (int ch = 0; ch < 32; ++ch) {
        if (ch + 1 < 32) copy_chunk((ch + 1) * 32, (ch + 1) & 1);
        cp_commit();
        cp_wait<1>();
        __syncthreads();
        const int buf = ch & 1;
#pragma unroll
        for (int s = 0; s < 4; ++s) {
            // slot (cq, h) holds global k = 8s + 2cq + h
            unsigned af[4][4], bf[4][2];
            const int ac = s * 8 + 2 * cq;          // A column of the k-pair
            const int bp = s * 4 + cq;              // B pair-row (k/2)
#pragma unroll
            for (int fm = 0; fm < 4; ++fm) {
                int r = wm + fm * 16 + g;
                float2 lo = *(const float2*)&As[buf][r][ac];       // k, k+1
                float2 hi = *(const float2*)&As[buf][r + 8][ac];
                af[fm][0] = __float_as_uint(lo.x);   // slot (cq, h=0)
                af[fm][2] = __float_as_uint(lo.y);   // slot (cq, h=1)
                af[fm][1] = __float_as_uint(hi.x);
                af[fm][3] = __float_as_uint(hi.y);
            }
#pragma unroll
            for (int fn = 0; fn < 4; ++fn) {
                int cn = wn + fn * 8 + g;
                float2 bv = *(const float2*)&Bs[buf][bp][cn * 2];  // k, k+1 at col cn
                bf[fn][0] = __float_as_uint(bv.x);
                bf[fn][1] = __float_as_uint(bv.y);
            }
#pragma unroll
            for (int fm = 0; fm < 4; ++fm)
#pragma unroll
                for (int fn = 0; fn < 4; ++fn)
                    mma_tf32(acc[fm][fn], af[fm], bf[fn]);
        }
        __syncthreads();
    }

    // epilogue: +bias, optional exact GELU + tf32 rounding (h feeds next GEMM)
    // D fragment mapping untouched by the k remap: c0,c1 -> (row g, cols 2cq,2cq+1).
#pragma unroll
    for (int fm = 0; fm < 4; ++fm) {
#pragma unroll
        for (int fn = 0; fn < 4; ++fn) {
            int row = m0 + wm + fm * 16 + g;
            int col = n0 + wn + fn * 8 + 2 * cq;
            float b0v = bias[col], b1v = bias[col + 1];
            float v00 = acc[fm][fn][0] + b0v;
            float v01 = acc[fm][fn][1] + b1v;
            float v10 = acc[fm][fn][2] + b0v;
            float v11 = acc[fm][fn][3] + b1v;
            if (do_gelu) {
                v00 = tf32_rna(gelu_exact(v00));
                v01 = tf32_rna(gelu_exact(v01));
                v10 = tf32_rna(gelu_exact(v10));
                v11 = tf32_rna(gelu_exact(v11));
            }
            *(float2*)(C + (size_t)row * DIM + col)       = make_float2(v00, v01);
            *(float2*)(C + (size_t)(row + 8) * DIM + col) = make_float2(v10, v11);
        }
    }
}

// ---------------- per-row LayerNorm + softmax-weighted combine --------------
// warp-per-expert: warp e owns expert e's full 1024-float row (32 regs/lane),
// LN stats via shuffles only; weighted-normalized rows staged in padded smem;
// 2 block barriers total (vs 16 in the naive per-expert loop).
__global__ __launch_bounds__(256) void combine_kernel(
    const float* __restrict__ y, const float* __restrict__ wts,
    const float* __restrict__ gamma, const float* __restrict__ beta,
    float* __restrict__ out)
{
    __shared__ float s_acc[8][1032];     // pad 8 floats: row stride 4128B (16B-aligned)
    const int b = blockIdx.x;
    const int warp = threadIdx.x >> 5, lane = threadIdx.x & 31;

    const float* yrow = y + ((size_t)warp * BATCH + b) * DIM;
    float4 v[8];
    float s = 0.f, ss = 0.f;
#pragma unroll
    for (int u = 0; u < 8; ++u) {
        v[u] = *(const float4*)(yrow + u * 128 + lane * 4);
        s  += v[u].x + v[u].y + v[u].z + v[u].w;
        ss += v[u].x * v[u].x + v[u].y * v[u].y + v[u].z * v[u].z + v[u].w * v[u].w;
    }
#pragma unroll
    for (int off = 16; off; off >>= 1) {
        s  += __shfl_xor_sync(0xffffffffu, s, off);
        ss += __shfl_xor_sync(0xffffffffu, ss, off);
    }
    const float mu  = s * (1.0f / 1024.0f);
    const float var = ss * (1.0f / 1024.0f) - mu * mu;
    const float inv = rsqrtf(var + 1e-5f);
    const float we  = wts[(size_t)b * 8 + warp];
#pragma unroll
    for (int u = 0; u < 8; ++u) {
        const int col = u * 128 + lane * 4;
        const float4 g4 = *(const float4*)(gamma + (size_t)warp * DIM + col);
        const float4 b4 = *(const float4*)(beta  + (size_t)warp * DIM + col);
        float4 r;
        r.x = we * ((v[u].x - mu) * inv * g4.x + b4.x);
        r.y = we * ((v[u].y - mu) * inv * g4.y + b4.y);
        r.z = we * ((v[u].z - mu) * inv * g4.z + b4.z);
        r.w = we * ((v[u].w - mu) * inv * g4.w + b4.w);
        *(float4*)&s_acc[warp][col] = r;
    }
    __syncthreads();
    // cross-expert sum: thread t handles cols 4t..4t+3 (LDS.128, conflict-free)
    const int col = threadIdx.x * 4;
    float4 a = *(const float4*)&s_acc[0][col];
#pragma unroll
    for (int e2 = 1; e2 < 8; ++e2) {
        const float4 q = *(const float4*)&s_acc[e2][col];
        a.x += q.x; a.y += q.y; a.z += q.z; a.w += q.w;
    }
    *(float4*)(out + (size_t)b * DIM + col) = a;
}

// ---------------- launch -----------------------------------------------------
extern "C" void kernel_launch(void* const* d_in, const int* in_sizes, int n_in,
                              void* d_out, int out_size) {
    const float* z_s      = (const float*)d_in[0];
    const float* z_e      = (const float*)d_in[1];
    const float* router_w = (const float*)d_in[2];
    const float* router_b = (const float*)d_in[3];
    const float* w1       = (const float*)d_in[4];
    const float* b1       = (const float*)d_in[5];
    const float* w2       = (const float*)d_in[6];
    const float* b2       = (const float*)d_in[7];
    const float* gamma    = (const float*)d_in[8];
    const float* beta     = (const float*)d_in[9];
    float* out = (float*)d_out;

    float *p_comb, *p_w1t, *p_w2t, *p_h, *p_y, *p_wts;
    cudaGetSymbolAddress((void**)&p_comb, g_combined);
    cudaGetSymbolAddress((void**)&p_w1t,  g_w1t);
    cudaGetSymbolAddress((void**)&p_w2t,  g_w2t);
    cudaGetSymbolAddress((void**)&p_h,    g_h);
    cudaGetSymbolAddress((void**)&p_y,    g_y);
    cudaGetSymbolAddress((void**)&p_wts,  g_wts);

    cudaFuncSetAttribute(gemm_tf32_kernel,
                         cudaFuncAttributeMaxDynamicSharedMemorySize, SMEM_BYTES);

    // prep: tf32-round activations; round + k-pair-interleave weights
    concat_round_kernel<<<(BATCH * DIM / 4) / 256, 256>>>(z_s, z_e, p_comb);
    interleave_round_kernel<<<(EXPERTS * DIM * DIM / 4) / 256, 256>>>(w1, p_w1t);
    interleave_round_kernel<<<(EXPERTS * DIM * DIM / 4) / 256, 256>>>(w2, p_w2t);

    router_kernel<<<BATCH / 8, 256>>>(z_s, z_e, router_w, router_b, p_wts);

    dim3 gg(DIM / 128, BATCH / 128, EXPERTS);   // (n, m, e): A reuse in L2 across n
    gemm_tf32_kernel<<<gg, 256, SMEM_BYTES>>>(p_comb, 0, p_w1t, b1,
                                              p_h, (size_t)BATCH * DIM, 1);
    gemm_tf32_kernel<<<gg, 256, SMEM_BYTES>>>(p_h, (size_t)BATCH * DIM, p_w2t, b2,
                                              p_y, (size_t)BATCH * DIM, 0);

    combine_kernel<<<BATCH, 256>>>(p_y, p_wts, gamma, beta, out);
    (void)in_sizes; (void)n_in; (void)out_size;
}

// round 13
// speedup vs baseline: 1.0277x; 1.0277x over previous
#include <cuda_runtime.h>
#include <cstdint>
#include <cstddef>

#define BATCH   16384
#define EXPERTS 8
#define DIM     1024

// ---------------- scratch (device globals; no allocations allowed) ----------
__device__ float g_combined[(size_t)BATCH * DIM];                 //  67 MB
__device__ float g_w1t[(size_t)EXPERTS * DIM * DIM];              //  33.5 MB (k-pair interleaved)
__device__ float g_w2t[(size_t)EXPERTS * DIM * DIM];              //  33.5 MB (k-pair interleaved)
__device__ float g_h[(size_t)EXPERTS * BATCH * DIM];              // 537 MB
__device__ float g_y[(size_t)EXPERTS * BATCH * DIM];              // 537 MB
__device__ float g_wts[(size_t)BATCH * EXPERTS];                  // 0.5 MB

// ---------------- helpers ---------------------------------------------------
__device__ __forceinline__ unsigned smem_u32(const void* p) {
    return (unsigned)__cvta_generic_to_shared(p);
}
__device__ __forceinline__ float tf32_rna(float x) {
    unsigned u;
    asm("cvt.rna.tf32.f32 %0, %1;" : "=r"(u) : "f"(x));
    return __uint_as_float(u);
}
__device__ __forceinline__ void cp_async16(unsigned dst, const void* src) {
    asm volatile("cp.async.cg.shared.global [%0], [%1], 16;\n" :: "r"(dst), "l"(src));
}
__device__ __forceinline__ void cp_commit() {
    asm volatile("cp.async.commit_group;\n");
}
template <int N>
__device__ __forceinline__ void cp_wait() {
    asm volatile("cp.async.wait_group %0;\n" :: "n"(N));
}
__device__ __forceinline__ void mma_tf32(float* d, const unsigned* a, const unsigned* b) {
    asm volatile(
        "mma.sync.aligned.m16n8k8.row.col.f32.tf32.tf32.f32 "
        "{%0,%1,%2,%3}, {%4,%5,%6,%7}, {%8,%9}, {%0,%1,%2,%3};\n"
        : "+f"(d[0]), "+f"(d[1]), "+f"(d[2]), "+f"(d[3])
        : "r"(a[0]), "r"(a[1]), "r"(a[2]), "r"(a[3]), "r"(b[0]), "r"(b[1]));
}
__device__ __forceinline__ float gelu_exact(float x) {
    return 0.5f * x * (1.0f + erff(x * 0.70710678118654752f));
}

// ---------------- prep kernels ----------------------------------------------
__global__ void concat_round_kernel(const float* __restrict__ z_s,
                                    const float* __restrict__ z_e,
                                    float* __restrict__ dst) {
    size_t f = ((size_t)blockIdx.x * 256 + threadIdx.x) * 4;   // float4 index
    size_t b = f >> 10;
    int col = (int)(f & 1023);
    float4 v;
    if (col < 512) v = *(const float4*)(z_s + b * 512 + col);
    else           v = *(const float4*)(z_e + b * 512 + (col - 512));
    v.x = tf32_rna(v.x); v.y = tf32_rna(v.y);
    v.z = tf32_rna(v.z); v.w = tf32_rna(v.w);
    *(float4*)(dst + f) = v;
}

// W [e][k][n] row-major -> Wt [e][p][n][h] (p=k/2, h=k&1), tf32-rounded.
// One launch handles BOTH weight tensors (first half of blocks: w1, second: w2).
#define WCHUNKS ((size_t)EXPERTS * DIM * DIM / 4)
__global__ void interleave_round_kernel(const float* __restrict__ W1,
                                        const float* __restrict__ W2,
                                        float* __restrict__ W1t,
                                        float* __restrict__ W2t) {
    size_t c = (size_t)blockIdx.x * 256 + threadIdx.x;  // float4 chunk index
    const float* W = W1; float* Wt = W1t;
    if (c >= WCHUNKS) { c -= WCHUNKS; W = W2; Wt = W2t; }
    size_t e   = c >> 18;                               // 2^18 chunks per expert
    size_t rem = c & ((1u << 18) - 1);
    int p  = (int)(rem >> 9);                           // 512 chunks per pair-row
    int n  = (int)(rem & 511) * 2;
    const float* We = W + e * (size_t)DIM * DIM;
    float4 v;
    v.x = tf32_rna(We[(size_t)(2 * p)     * DIM + n]);
    v.y = tf32_rna(We[(size_t)(2 * p + 1) * DIM + n]);
    v.z = tf32_rna(We[(size_t)(2 * p)     * DIM + n + 1]);
    v.w = tf32_rna(We[(size_t)(2 * p + 1) * DIM + n + 1]);
    *(float4*)(Wt + e * (size_t)DIM * DIM + (rem >> 9) * 2048 + (size_t)(rem & 511) * 4) = v;
}

// ---------------- router (softmax gates) ------------------------------------
// R5 ncu: 41.5us with L1tex 76.7% (every warp re-read 32KB router_w).
// Stage router_w in smem once per block; loop reads become conflict-free LDS.
__global__ __launch_bounds__(256) void router_kernel(const float* __restrict__ z_s,
                                                     const float* __restrict__ z_e,
                                                     const float* __restrict__ rw,
                                                     const float* __restrict__ rb,
                                                     float* __restrict__ wts) {
    __shared__ float s_rw[1024 * 8];     // 32 KB
    int warp = threadIdx.x >> 5, lane = threadIdx.x & 31;
#pragma unroll
    for (int j = 0; j < 8; ++j) {
        int idx = (threadIdx.x + j * 256) * 4;
        *(float4*)&s_rw[idx] = *(const float4*)(rw + idx);
    }
    __syncthreads();

    int b = blockIdx.x * 8 + warp;
    const float* zs = z_s + (size_t)b * 512;
    const float* ze = z_e + (size_t)b * 512;
    float acc[8];
#pragma unroll
    for (int e = 0; e < 8; ++e) acc[e] = 0.f;
    for (int c = lane; c < 1024; c += 32) {
        float x = (c < 512) ? zs[c] : ze[c - 512];
        float4 wa = *(const float4*)&s_rw[c * 8];
        float4 wb = *(const float4*)&s_rw[c * 8 + 4];
        acc[0] += x * wa.x; acc[1] += x * wa.y; acc[2] += x * wa.z; acc[3] += x * wa.w;
        acc[4] += x * wb.x; acc[5] += x * wb.y; acc[6] += x * wb.z; acc[7] += x * wb.w;
    }
#pragma unroll
    for (int e = 0; e < 8; ++e)
#pragma unroll
        for (int off = 16; off; off >>= 1)
            acc[e] += __shfl_xor_sync(0xffffffffu, acc[e], off);
    if (lane == 0) {
        float l[8], m = -1e30f;
#pragma unroll
        for (int e = 0; e < 8; ++e) { l[e] = acc[e] + rb[e]; m = fmaxf(m, l[e]); }
        float s = 0.f;
#pragma unroll
        for (int e = 0; e < 8; ++e) { l[e] = expf(l[e] - m); s += l[e]; }
        float inv = 1.0f / s;
#pragma unroll
        for (int e = 0; e < 8; ++e) wts[(size_t)b * 8 + e] = l[e] * inv;
    }
}

// ---------------- tf32 mma.sync GEMM (the R5-passing design + 3-stage loop) --
// C[e] = A[e] (M x K=1024, row-major) @ W[e] (K x N=1024) + bias
// block tile 128x128, k-chunk 32, 8 warps (2x4), warp tile 64x32 of m16n8k8.
// k-slot remap: mma step s, thread cq, half h  <->  global k = 8s + 2*cq + h:
//   A thread k-pair column-adjacent (LDS.64); B pre-interleaved k-pairs (LDS.64).
// 3-stage cp.async pipeline, ONE __syncthreads per chunk:
//   iter i: wait<1>; sync; compute(i) from stage i%3; copy(i+2) into (i+2)%3.
//   copy(i+2)'s stage was last read by compute(i-1), finished before this
//   iteration's barrier -> race-free with a single barrier.
#define A_ST 40
#define B_ST 264                          /* floats per pair-row (132 x 8B) */
#define A_STAGE_F (128 * A_ST)            /* 5120 floats */
#define B_STAGE_F (16 * B_ST)             /* 4224 floats */
#define STAGE_F   (A_STAGE_F + B_STAGE_F) /* 9344 floats */
#define STAGE_BYTES (STAGE_F * 4)         /* 37376 B */
#define N_STAGE   3
#define GEMM_SMEM (N_STAGE * STAGE_BYTES) /* 112128 B; 2 CTAs = 224 KB <= 228 KB */

__global__ __launch_bounds__(256, 2) void gemm_tf32_kernel(
    const float* __restrict__ Abase, size_t a_estride,
    const float* __restrict__ Wtbase,
    const float* __restrict__ biasBase,
    float* __restrict__ Cbase, size_t c_estride,
    int do_gelu)
{
    extern __shared__ float sm[];

    const int e = blockIdx.z;
    const float* A    = Abase + (size_t)e * a_estride;
    const float* Wt   = Wtbase + (size_t)e * DIM * DIM;
    const float* bias = biasBase + (size_t)e * DIM;
    float* C          = Cbase + (size_t)e * c_estride;

    const int n0 = blockIdx.x * 128;
    const int m0 = blockIdx.y * 128;
    const int tid = threadIdx.x;
    const int warp = tid >> 5, lane = tid & 31;
    const int wm = (warp >> 2) * 64;      // 2 warps in M
    const int wn = (warp & 3) * 32;       // 4 warps in N
    const int g  = lane >> 2, cq = lane & 3;

    // per-thread copy descriptors (stage-0 smem addrs; stage s = +s*STAGE_BYTES)
    const float* gA[4]; unsigned dA0[4];
    const float* gB[4]; unsigned dB0[4];
#pragma unroll
    for (int i = 0; i < 4; ++i) {
        int f   = tid + i * 256;
        int row = f >> 3, k4 = (f & 7) * 4;
        gA[i]   = A + (size_t)(m0 + row) * DIM + k4;
        dA0[i]  = smem_u32(sm + row * A_ST + k4);
        // B: 16B chunk f covers pair-row p = f>>6, columns n..n+1, both halves.
        int p = f >> 6, nn = (f & 63) * 2;
        gB[i]   = Wt + ((size_t)p * DIM + n0 + nn) * 2;
        dB0[i]  = smem_u32(sm + A_STAGE_F + p * B_ST + nn * 2);
    }

    float acc[4][4][4];
#pragma unroll
    for (int a = 0; a < 4; ++a)
#pragma unroll
        for (int b = 0; b < 4; ++b)
#pragma unroll
            for (int k = 0; k < 4; ++k) acc[a][b][k] = 0.f;

    auto copy_chunk = [&](int ch, int stg) {
        const unsigned so = stg * STAGE_BYTES;
        const int k0 = ch * 32;
#pragma unroll
        for (int i = 0; i < 4; ++i) cp_async16(dA0[i] + so, gA[i] + k0);
        // chunk advance in Wt: 16 pair-rows * 1024 n * 2 halves = k0 * DIM floats
#pragma unroll
        for (int i = 0; i < 4; ++i) cp_async16(dB0[i] + so, gB[i] + (size_t)k0 * DIM);
        cp_commit();
    };

    // prologue: chunks 0,1 into stages 0,1
    copy_chunk(0, 0);
    copy_chunk(1, 1);

#pragma unroll 1
    for (int i = 0; i < 32; ++i) {
        if (i < 31) cp_wait<1>(); else cp_wait<0>();
        __syncthreads();                       // chunk i staged for all threads
        const float* base = sm + (i % 3) * STAGE_F;
        const float* Ab = base;
        const float* Bb = base + A_STAGE_F;
#pragma unroll
        for (int s = 0; s < 4; ++s) {
            // slot (cq, h) holds global k = 8s + 2cq + h
            unsigned af[4][4], bf[4][2];
            const int ac = s * 8 + 2 * cq;          // A column of the k-pair
            const int bp = s * 4 + cq;              // B pair-row (k/2)
#pragma unroll
            for (int fm = 0; fm < 4; ++fm) {
                int r = wm + fm * 16 + g;
                float2 lo = *(const float2*)(Ab + r * A_ST + ac);       // k, k+1
                float2 hi = *(const float2*)(Ab + (r + 8) * A_ST + ac);
                af[fm][0] = __float_as_uint(lo.x);   // slot (cq, h=0)
                af[fm][2] = __float_as_uint(lo.y);   // slot (cq, h=1)
                af[fm][1] = __float_as_uint(hi.x);
                af[fm][3] = __float_as_uint(hi.y);
            }
#pragma unroll
            for (int fn = 0; fn < 4; ++fn) {
                int cn = wn + fn * 8 + g;
                float2 bv = *(const float2*)(Bb + bp * B_ST + cn * 2);  // k, k+1
                bf[fn][0] = __float_as_uint(bv.x);
                bf[fn][1] = __float_as_uint(bv.y);
            }
#pragma unroll
            for (int fm = 0; fm < 4; ++fm)
#pragma unroll
                for (int fn = 0; fn < 4; ++fn)
                    mma_tf32(acc[fm][fn], af[fm], bf[fn]);
        }
        if (i + 2 <= 31) copy_chunk(i + 2, (i + 2) % 3);
    }

    // epilogue: +bias, optional exact GELU + tf32 rounding (h feeds next GEMM)
#pragma unroll
    for (int fm = 0; fm < 4; ++fm) {
#pragma unroll
        for (int fn = 0; fn < 4; ++fn) {
            int row = m0 + wm + fm * 16 + g;
            int col = n0 + wn + fn * 8 + 2 * cq;
            float b0v = bias[col], b1v = bias[col + 1];
            float v00 = acc[fm][fn][0] + b0v;
            float v01 = acc[fm][fn][1] + b1v;
            float v10 = acc[fm][fn][2] + b0v;
            float v11 = acc[fm][fn][3] + b1v;
            if (do_gelu) {
                v00 = tf32_rna(gelu_exact(v00));
                v01 = tf32_rna(gelu_exact(v01));
                v10 = tf32_rna(gelu_exact(v10));
                v11 = tf32_rna(gelu_exact(v11));
            }
            *(float2*)(C + (size_t)row * DIM + col)       = make_float2(v00, v01);
            *(float2*)(C + (size_t)(row + 8) * DIM + col) = make_float2(v10, v11);
        }
    }
}

// ---------------- per-row LayerNorm + softmax-weighted combine --------------
// warp-per-expert: warp e owns expert e's full 1024-float row; LN via shuffles;
// weighted rows staged in padded smem; one block barrier total.
__global__ __launch_bounds__(256) void combine_kernel(
    const float* __restrict__ y, const float* __restrict__ wts,
    const float* __restrict__ gamma, const float* __restrict__ beta,
    float* __restrict__ out)
{
    __shared__ float s_acc[8][1032];
    const int b = blockIdx.x;
    const int warp = threadIdx.x >> 5, lane = threadIdx.x & 31;

    const float* yrow = y + ((size_t)warp * BATCH + b) * DIM;
    float4 v[8], g4[8], b4[8];
    float s = 0.f, ss = 0.f;
#pragma unroll
    for (int u = 0; u < 8; ++u) {
        v[u] = *(const float4*)(yrow + u * 128 + lane * 4);
        s  += v[u].x + v[u].y + v[u].z + v[u].w;
        ss += v[u].x * v[u].x + v[u].y * v[u].y + v[u].z * v[u].z + v[u].w * v[u].w;
    }
    // gamma/beta loads issued before the shuffle chain: latency overlaps it
#pragma unroll
    for (int u = 0; u < 8; ++u) {
        const int col = u * 128 + lane * 4;
        g4[u] = *(const float4*)(gamma + (size_t)warp * DIM + col);
        b4[u] = *(const float4*)(beta  + (size_t)warp * DIM + col);
    }
#pragma unroll
    for (int off = 16; off; off >>= 1) {
        s  += __shfl_xor_sync(0xffffffffu, s, off);
        ss += __shfl_xor_sync(0xffffffffu, ss, off);
    }
    const float mu  = s * (1.0f / 1024.0f);
    const float var = ss * (1.0f / 1024.0f) - mu * mu;
    const float inv = rsqrtf(var + 1e-5f);
    const float we  = wts[(size_t)b * 8 + warp];
#pragma unroll
    for (int u = 0; u < 8; ++u) {
        const int col = u * 128 + lane * 4;
        float4 r;
        r.x = we * ((v[u].x - mu) * inv * g4[u].x + b4[u].x);
        r.y = we * ((v[u].y - mu) * inv * g4[u].y + b4[u].y);
        r.z = we * ((v[u].z - mu) * inv * g4[u].z + b4[u].z);
        r.w = we * ((v[u].w - mu) * inv * g4[u].w + b4[u].w);
        *(float4*)&s_acc[warp][col] = r;
    }
    __syncthreads();
    const int col = threadIdx.x * 4;
    float4 a = *(const float4*)&s_acc[0][col];
#pragma unroll
    for (int e2 = 1; e2 < 8; ++e2) {
        const float4 q = *(const float4*)&s_acc[e2][col];
        a.x += q.x; a.y += q.y; a.z += q.z; a.w += q.w;
    }
    *(float4*)(out + (size_t)b * DIM + col) = a;
}

// ---------------- launch -----------------------------------------------------
extern "C" void kernel_launch(void* const* d_in, const int* in_sizes, int n_in,
                              void* d_out, int out_size) {
    const float* z_s      = (const float*)d_in[0];
    const float* z_e      = (const float*)d_in[1];
    const float* router_w = (const float*)d_in[2];
    const float* router_b = (const float*)d_in[3];
    const float* w1       = (const float*)d_in[4];
    const float* b1       = (const float*)d_in[5];
    const float* w2       = (const float*)d_in[6];
    const float* b2       = (const float*)d_in[7];
    const float* gamma    = (const float*)d_in[8];
    const float* beta     = (const float*)d_in[9];
    float* out = (float*)d_out;

    float *p_comb, *p_w1t, *p_w2t, *p_h, *p_y, *p_wts;
    cudaGetSymbolAddress((void**)&p_comb, g_combined);
    cudaGetSymbolAddress((void**)&p_w1t,  g_w1t);
    cudaGetSymbolAddress((void**)&p_w2t,  g_w2t);
    cudaGetSymbolAddress((void**)&p_h,    g_h);
    cudaGetSymbolAddress((void**)&p_y,    g_y);
    cudaGetSymbolAddress((void**)&p_wts,  g_wts);

    cudaFuncSetAttribute(gemm_tf32_kernel,
                         cudaFuncAttributeMaxDynamicSharedMemorySize, GEMM_SMEM);

    // prep: tf32-round activations; round + k-pair-interleave both weights
    concat_round_kernel<<<(BATCH * DIM / 4) / 256, 256>>>(z_s, z_e, p_comb);
    interleave_round_kernel<<<(unsigned)(2 * WCHUNKS / 256), 256>>>(w1, w2, p_w1t, p_w2t);

    router_kernel<<<BATCH / 8, 256>>>(z_s, z_e, router_w, router_b, p_wts);

    dim3 gg(DIM / 128, BATCH / 128, EXPERTS);   // x=n fastest: A tiles reuse in L2
    gemm_tf32_kernel<<<gg, 256, GEMM_SMEM>>>(p_comb, 0, p_w1t, b1,
                                             p_h, (size_t)BATCH * DIM, 1);
    gemm_tf32_kernel<<<gg, 256, GEMM_SMEM>>>(p_h, (size_t)BATCH * DIM, p_w2t, b2,
                                             p_y, (size_t)BATCH * DIM, 0);

    combine_kernel<<<BATCH, 256>>>(p_y, p_wts, gamma, beta, out);
    (void)in_sizes; (void)n_in; (void)out_size;
}